// round 7
// baseline (speedup 1.0000x reference)
#include <cuda_runtime.h>
#include <cuda_bf16.h>
#include <cstdint>

// Swin window attention. R7: FULLY FUSED single kernel, one block per window.
// x -> qkv (tf32 mma) -> S (mma) -> softmax -> PV (mma) -> proj (mma) -> out.
// B=64, H=W=56, C=128, heads=4, hd=32, ws=7, L=49. 4096 windows.
// All intermediates in smem; HBM traffic = x (100MB) + out (103MB) only.

#define NWIN 4096

__device__ __forceinline__ uint32_t f2tf32(float x) {
    uint32_t r;
    asm("cvt.rna.tf32.f32 %0, %1;" : "=r"(r) : "f"(x));
    return r;
}
__device__ __forceinline__ void mma_tf32(float (&d)[4], const uint32_t* a, const uint32_t* b) {
    asm volatile("mma.sync.aligned.m16n8k8.row.col.f32.tf32.tf32.f32 "
                 "{%0,%1,%2,%3}, {%4,%5,%6,%7}, {%8,%9}, {%0,%1,%2,%3};"
                 : "+f"(d[0]), "+f"(d[1]), "+f"(d[2]), "+f"(d[3])
                 : "r"(a[0]), "r"(a[1]), "r"(a[2]), "r"(a[3]), "r"(b[0]), "r"(b[1]));
}

// smem word offsets (strides mod 32: 132=>4, 72=>8, 136=>8 -> all frag loads conflict-free)
#define OFF_X  0        // sX: 64 x 132 tf32 (x tile; reused as O after PV)
#define OFF_Q  8448     // sQ: 64 x 132 (q all heads, col = head*32+d)
#define OFF_KT 16896    // sKT: 128 x 72 ([head*32+d][l])
#define OFF_V  26112    // sV: 64 x 136 ([l][head*32+d])
#define OFF_S  34816    // sS: 4 heads x 64 x 72 fp32 (S, then P tf32 bits)
#define SMEM_WORDS 53248
#define SMEM_BYTES (SMEM_WORDS * 4)   // 212992

__global__ __launch_bounds__(256, 1) void fused_win_attn(
    const float* __restrict__ x, const float* __restrict__ qkv_w,
    const float* __restrict__ qkv_b, const int* __restrict__ relidx,
    const float* __restrict__ mask, const float* __restrict__ relt,
    const float* __restrict__ proj_w, const float* __restrict__ proj_b,
    float* __restrict__ out)
{
    extern __shared__ uint32_t sm[];
    uint32_t* sX  = sm + OFF_X;
    uint32_t* sQ  = sm + OFF_Q;
    uint32_t* sKT = sm + OFF_KT;
    uint32_t* sV  = sm + OFF_V;
    float*    sS  = (float*)(sm + OFF_S);

    int tid = threadIdx.x, lane = tid & 31, warp = tid >> 5;
    int g = lane >> 2, t = lane & 3;
    int widx = blockIdx.x;
    int bimg = widx >> 6, win = widx & 63;
    int ybase = (win >> 3) * 7, xbase = (win & 7) * 7;
    const float* maskp = mask + (size_t)win * 2401;

    // ---- stage 0: load x window (49x128, rows 49..63 zero) as tf32 ----
    for (int i = tid; i < 2048; i += 256) {
        int l = i >> 5, c4 = (i & 31) << 2;
        float4 v = make_float4(0.f, 0.f, 0.f, 0.f);
        if (l < 49) {
            int wy = l / 7, wx = l - wy * 7;
            v = *(const float4*)(x + (((size_t)(bimg * 56 + ybase + wy)) * 56
                                      + xbase + wx) * 128 + c4);
        }
        *(uint4*)&sX[l * 132 + c4] =
            make_uint4(f2tf32(v.x), f2tf32(v.y), f2tf32(v.z), f2tf32(v.w));
    }
    __syncthreads();

    // ---- stage 1: qkv = x @ qkv_w + b  (64x384, warps 2m x 4n, s-loop) ----
    {
        int mg = warp >> 2, ng = warp & 3;
        int m0 = mg * 32;
#pragma unroll 1
        for (int s = 0; s < 3; s++) {
            const float* Wp = qkv_w + s * 128 + ng * 32 + g;
            float acc[2][4][4] = {};
#pragma unroll
            for (int k0 = 0; k0 < 128; k0 += 8) {
                uint32_t b[4][2];
                const float* w0 = Wp + (size_t)(k0 + t) * 384;
                const float* w1 = w0 + 4 * 384;
#pragma unroll
                for (int nt = 0; nt < 4; nt++) {
                    b[nt][0] = f2tf32(__ldg(w0 + nt * 8));
                    b[nt][1] = f2tf32(__ldg(w1 + nt * 8));
                }
                uint32_t a[2][4];
#pragma unroll
                for (int mt = 0; mt < 2; mt++) {
                    int base = (m0 + mt * 16 + g) * 132 + k0 + t;
                    a[mt][0] = sX[base];
                    a[mt][1] = sX[base + 8 * 132];
                    a[mt][2] = sX[base + 4];
                    a[mt][3] = sX[base + 8 * 132 + 4];
                }
#pragma unroll
                for (int mt = 0; mt < 2; mt++)
#pragma unroll
                    for (int nt = 0; nt < 4; nt++)
                        mma_tf32(acc[mt][nt], a[mt], b[nt]);
            }
            // epilogue: + bias, store tf32 into sQ / sKT(transposed) / sV
            float bb[4][2];
#pragma unroll
            for (int nt = 0; nt < 4; nt++) {
                int c = ng * 32 + nt * 8 + 2 * t;
                bb[nt][0] = __ldg(qkv_b + s * 128 + c);
                bb[nt][1] = __ldg(qkv_b + s * 128 + c + 1);
            }
#pragma unroll
            for (int mt = 0; mt < 2; mt++)
#pragma unroll
                for (int h = 0; h < 2; h++) {
                    int row = m0 + mt * 16 + g + h * 8;
#pragma unroll
                    for (int nt = 0; nt < 4; nt++) {
                        int c = ng * 32 + nt * 8 + 2 * t;
                        uint32_t v0 = f2tf32(acc[mt][nt][2 * h]     + bb[nt][0]);
                        uint32_t v1 = f2tf32(acc[mt][nt][2 * h + 1] + bb[nt][1]);
                        if (s == 0) {
                            sQ[row * 132 + c] = v0;
                            sQ[row * 132 + c + 1] = v1;
                        } else if (s == 1) {
                            sKT[c * 72 + row] = v0;
                            sKT[(c + 1) * 72 + row] = v1;
                        } else {
                            sV[row * 136 + c] = v0;
                            sV[row * 136 + c + 1] = v1;
                        }
                    }
                }
        }
    }
    __syncthreads();

    // ---- stage 2: S = scale*Q@K^T + bias + mask (warp: head=w>>1, mhalf=w&1) ----
    {
        int head = warp >> 1, m0s = (warp & 1) * 32;
        float acc[2][8][4] = {};
#pragma unroll
        for (int k0 = 0; k0 < 32; k0 += 8) {
            uint32_t a[2][4];
#pragma unroll
            for (int mt = 0; mt < 2; mt++) {
                int base = (m0s + mt * 16 + g) * 132 + head * 32 + k0 + t;
                a[mt][0] = sQ[base];
                a[mt][1] = sQ[base + 8 * 132];
                a[mt][2] = sQ[base + 4];
                a[mt][3] = sQ[base + 8 * 132 + 4];
            }
#pragma unroll
            for (int nt = 0; nt < 8; nt++) {
                uint32_t b[2];
                int bb = (head * 32 + k0 + t) * 72 + nt * 8 + g;
                b[0] = sKT[bb];
                b[1] = sKT[bb + 4 * 72];
#pragma unroll
                for (int mt = 0; mt < 2; mt++)
                    mma_tf32(acc[mt][nt], a[mt], b);
            }
        }
        float* Sh = sS + head * 4608;
        const float scale = 0.17677669529663687f;
#pragma unroll
        for (int mt = 0; mt < 2; mt++)
#pragma unroll
            for (int h = 0; h < 2; h++) {
                int i = m0s + mt * 16 + g + h * 8;
                if (i < 49) {
#pragma unroll
                    for (int nt = 0; nt < 8; nt++)
#pragma unroll
                        for (int e = 0; e < 2; e++) {
                            int j = nt * 8 + 2 * t + e;
                            float val = -1e30f;
                            if (j < 49) {
                                int ij = i * 49 + j;
                                val = acc[mt][nt][2 * h + e] * scale
                                    + __ldg(relt + __ldg(relidx + ij) * 4 + head)
                                    + __ldg(maskp + ij);
                            }
                            Sh[i * 72 + j] = val;
                        }
                }
            }
    }
    __syncthreads();

    // ---- stage 3: softmax per (head,row), write P as tf32 bits ----
    {
        int head = tid >> 6, row = tid & 63;
        if (row < 49) {
            float* Sh = sS + head * 4608 + row * 72;
            uint32_t* Pu = (uint32_t*)Sh;
            float mx = -1e30f;
            for (int j = 0; j < 49; j++) mx = fmaxf(mx, Sh[j]);
            float sum = 0.f;
            for (int j = 0; j < 49; j++) {
                float e = __expf(Sh[j] - mx);
                Sh[j] = e;
                sum += e;
            }
            float inv = 1.f / sum;
            for (int j = 0; j < 49; j++) Pu[j] = f2tf32(Sh[j] * inv);
            for (int j = 49; j < 64; j++) Pu[j] = 0u;
        }
    }
    __syncthreads();

    // ---- stage 4: O = P @ V  -> sX (reused as O, tf32) ----
    {
        int head = warp >> 1, m0s = (warp & 1) * 32;
        const uint32_t* Pu = (const uint32_t*)(sS + head * 4608);
        float acc[2][4][4] = {};
#pragma unroll
        for (int k0 = 0; k0 < 64; k0 += 8) {
            uint32_t a[2][4];
#pragma unroll
            for (int mt = 0; mt < 2; mt++) {
                int base = (m0s + mt * 16 + g) * 72 + k0 + t;
                a[mt][0] = Pu[base];
                a[mt][1] = Pu[base + 8 * 72];
                a[mt][2] = Pu[base + 4];
                a[mt][3] = Pu[base + 8 * 72 + 4];
            }
#pragma unroll
            for (int nt = 0; nt < 4; nt++) {
                uint32_t b[2];
                int bb = (k0 + t) * 136 + head * 32 + nt * 8 + g;
                b[0] = sV[bb];
                b[1] = sV[bb + 4 * 136];
#pragma unroll
                for (int mt = 0; mt < 2; mt++)
                    mma_tf32(acc[mt][nt], a[mt], b);
            }
        }
#pragma unroll
        for (int mt = 0; mt < 2; mt++)
#pragma unroll
            for (int h = 0; h < 2; h++) {
                int row = m0s + mt * 16 + g + h * 8;
#pragma unroll
                for (int nt = 0; nt < 4; nt++) {
                    int c = head * 32 + nt * 8 + 2 * t;
                    sX[row * 132 + c]     = f2tf32(acc[mt][nt][2 * h]);
                    sX[row * 132 + c + 1] = f2tf32(acc[mt][nt][2 * h + 1]);
                }
            }
    }
    __syncthreads();

    // ---- stage 5: out = O @ proj_w + b  (warps 2m x 4n) ----
    {
        int mg = warp >> 2, ng = warp & 3;
        int m0 = mg * 32, n0 = ng * 32;
        const float* Wp = proj_w + n0 + g;
        float acc[2][4][4] = {};
#pragma unroll
        for (int k0 = 0; k0 < 128; k0 += 8) {
            uint32_t b[4][2];
            const float* w0 = Wp + (size_t)(k0 + t) * 128;
            const float* w1 = w0 + 4 * 128;
#pragma unroll
            for (int nt = 0; nt < 4; nt++) {
                b[nt][0] = f2tf32(__ldg(w0 + nt * 8));
                b[nt][1] = f2tf32(__ldg(w1 + nt * 8));
            }
            uint32_t a[2][4];
#pragma unroll
            for (int mt = 0; mt < 2; mt++) {
                int base = (m0 + mt * 16 + g) * 132 + k0 + t;
                a[mt][0] = sX[base];
                a[mt][1] = sX[base + 8 * 132];
                a[mt][2] = sX[base + 4];
                a[mt][3] = sX[base + 8 * 132 + 4];
            }
#pragma unroll
            for (int mt = 0; mt < 2; mt++)
#pragma unroll
                for (int nt = 0; nt < 4; nt++)
                    mma_tf32(acc[mt][nt], a[mt], b[nt]);
        }
        float bb[4][2];
#pragma unroll
        for (int nt = 0; nt < 4; nt++) {
            int d = n0 + nt * 8 + 2 * t;
            bb[nt][0] = __ldg(proj_b + d);
            bb[nt][1] = __ldg(proj_b + d + 1);
        }
#pragma unroll
        for (int mt = 0; mt < 2; mt++)
#pragma unroll
            for (int h = 0; h < 2; h++) {
                int row = m0 + mt * 16 + g + h * 8;
                if (row < 49) {
                    int wy = row / 7, wx = row - wy * 7;
                    float* op = out + (((size_t)(bimg * 56 + ybase + wy)) * 56
                                       + xbase + wx) * 128;
#pragma unroll
                    for (int nt = 0; nt < 4; nt++) {
                        int d = n0 + nt * 8 + 2 * t;
                        *(float2*)&op[d] =
                            make_float2(acc[mt][nt][2 * h]     + bb[nt][0],
                                        acc[mt][nt][2 * h + 1] + bb[nt][1]);
                    }
                }
            }
    }
}

// ---------------------------------------------------------------------------
extern "C" void kernel_launch(void* const* d_in, const int* in_sizes, int n_in,
                              void* d_out, int out_size)
{
    const float* x      = nullptr;
    const int*   relidx = nullptr;
    const float* mask   = nullptr;
    const float* qkv_w  = nullptr;
    const float* qkv_b  = nullptr;
    const float* relt   = nullptr;
    const float* proj_w = nullptr;
    const float* proj_b = nullptr;

    for (int i = 0; i < n_in; i++) {
        switch (in_sizes[i]) {
            case 25690112: x      = (const float*)d_in[i]; break;
            case 2401:     relidx = (const int*)  d_in[i]; break;
            case 153664:   mask   = (const float*)d_in[i]; break;
            case 49152:    qkv_w  = (const float*)d_in[i]; break;
            case 384:      qkv_b  = (const float*)d_in[i]; break;
            case 676:      relt   = (const float*)d_in[i]; break;
            case 16384:    proj_w = (const float*)d_in[i]; break;
            case 128:      proj_b = (const float*)d_in[i]; break;
            default: break;
        }
    }

    cudaFuncSetAttribute(fused_win_attn,
                         cudaFuncAttributeMaxDynamicSharedMemorySize, SMEM_BYTES);

    fused_win_attn<<<NWIN, 256, SMEM_BYTES>>>(
        x, qkv_w, qkv_b, relidx, mask, relt, proj_w, proj_b, (float*)d_out);
}

// round 8
// speedup vs baseline: 1.2317x; 1.2317x over previous
#include <cuda_runtime.h>
#include <cuda_bf16.h>
#include <cstdint>

// Swin window attention. R8 = R6 skeleton + W-load software pipelining (qkv/proj)
// + precomputed bias+mask table for attention.
// B=64, H=W=56, C=128, heads=4, hd=32, ws=7, L=49.

#define TOKENS   200704
#define WH_TOTAL 16384
#define QKV_ELEMS (3ull * 16384ull * 49ull * 32ull)
#define ATT_ELEMS ((size_t)TOKENS * 128)
#define COMB_ELEMS (64 * 4 * 2401)   // [win][head][ij]

__device__ float g_qkv[QKV_ELEMS];   // [(s*16384 + wh)*49 + l]*32 + d
__device__ float g_att[ATT_ELEMS];   // [b,h,w,c] pre-projection
__device__ float g_comb[COMB_ELEMS]; // relt[relidx[ij]][head] + mask[win][ij]

// ---------------------------------------------------------------------------
__device__ __forceinline__ uint32_t f2tf32(float x) {
    uint32_t r;
    asm("cvt.rna.tf32.f32 %0, %1;" : "=r"(r) : "f"(x));
    return r;
}
__device__ __forceinline__ void mma_tf32(float (&d)[4], const uint32_t* a, const uint32_t* b) {
    asm volatile("mma.sync.aligned.m16n8k8.row.col.f32.tf32.tf32.f32 "
                 "{%0,%1,%2,%3}, {%4,%5,%6,%7}, {%8,%9}, {%0,%1,%2,%3};"
                 : "+f"(d[0]), "+f"(d[1]), "+f"(d[2]), "+f"(d[3])
                 : "r"(a[0]), "r"(a[1]), "r"(a[2]), "r"(a[3]), "r"(b[0]), "r"(b[1]));
}

#define A_STR 132   // A smem stride (frag lane bank = 4g+t, conflict-free)
#define SM_A_BYTES (128 * A_STR * 4)   // 67584

// ---------------------------------------------------------------------------
// Kernel 0: combine relative-position bias and window mask.
// ---------------------------------------------------------------------------
__global__ __launch_bounds__(256) void combine_bias(
    const int* __restrict__ relidx, const float* __restrict__ mask,
    const float* __restrict__ relt)
{
    int i = blockIdx.x * 256 + threadIdx.x;
    if (i < COMB_ELEMS) {
        int ij = i % 2401;
        int wh = i / 2401;
        int head = wh & 3, win = wh >> 2;
        g_comb[i] = __ldg(relt + __ldg(relidx + ij) * 4 + head)
                  + __ldg(mask + (size_t)win * 2401 + ij);
    }
}

// ---------------------------------------------------------------------------
// Kernel 1: QKV GEMM. grid=1568, 256 threads (8 warps: 2m x 4n). A in smem,
// W fragments prefetched from gmem with distance-1 pipeline. Scatter epilogue.
// ---------------------------------------------------------------------------
__global__ __launch_bounds__(256, 2) void qkv_gemm_mma(
    const float* __restrict__ A, const float* __restrict__ W,
    const float* __restrict__ bias)
{
    extern __shared__ uint32_t As[];

    int tid = threadIdx.x, bm = blockIdx.x;
    int lane = tid & 31, warp = tid >> 5;
    int g = lane >> 2, t = lane & 3;
    int m0 = (warp >> 2) * 64, n0 = (warp & 3) * 32;
    int head = warp & 3;

    {
        const float4* Ap = (const float4*)(A + (size_t)bm * 128 * 128);
        for (int i = tid; i < 4096; i += 256) {
            int r = i >> 5, c = (i & 31) << 2;
            float4 v = Ap[i];
            uint4 u = make_uint4(f2tf32(v.x), f2tf32(v.y), f2tf32(v.z), f2tf32(v.w));
            *(uint4*)&As[r * A_STR + c] = u;
        }
    }

    int whbase[8], lwin8[8];
#pragma unroll
    for (int mt = 0; mt < 4; mt++)
#pragma unroll
        for (int h = 0; h < 2; h++) {
            int m = bm * 128 + m0 + mt * 16 + g + h * 8;
            int bimg = m / 3136;
            int rem  = m - bimg * 3136;
            int y = rem / 56, xx = rem - y * 56;
            int nhi = y / 7,  wy = y - nhi * 7;
            int nwi = xx / 7, wx = xx - nwi * 7;
            whbase[mt * 2 + h] = (bimg * 64 + nhi * 8 + nwi) * 4 + head;
            lwin8[mt * 2 + h]  = wy * 7 + wx;
        }
    __syncthreads();

#pragma unroll 1
    for (int s = 0; s < 3; s++) {
        const float* Wp = W + s * 128 + n0 + g;
        float acc[4][4][4] = {};

        // prefetch k0=0 (converted)
        uint32_t bv[8];
        {
            const float* w0 = Wp + (size_t)t * 384;
            const float* w1 = w0 + 4 * 384;
#pragma unroll
            for (int nt = 0; nt < 4; nt++) {
                bv[nt]     = f2tf32(__ldg(w0 + nt * 8));
                bv[4 + nt] = f2tf32(__ldg(w1 + nt * 8));
            }
        }
#pragma unroll
        for (int k0 = 0; k0 < 128; k0 += 8) {
            uint32_t bc[8];
#pragma unroll
            for (int j = 0; j < 8; j++) bc[j] = bv[j];
            if (k0 < 120) {
                const float* w0 = Wp + (size_t)(k0 + 8 + t) * 384;
                const float* w1 = w0 + 4 * 384;
#pragma unroll
                for (int nt = 0; nt < 4; nt++) {
                    bv[nt]     = f2tf32(__ldg(w0 + nt * 8));
                    bv[4 + nt] = f2tf32(__ldg(w1 + nt * 8));
                }
            }
            uint32_t a[4][4];
#pragma unroll
            for (int mt = 0; mt < 4; mt++) {
                int base = (m0 + mt * 16 + g) * A_STR + k0 + t;
                a[mt][0] = As[base];
                a[mt][1] = As[base + 8 * A_STR];
                a[mt][2] = As[base + 4];
                a[mt][3] = As[base + 8 * A_STR + 4];
            }
#pragma unroll
            for (int mt = 0; mt < 4; mt++)
#pragma unroll
                for (int nt = 0; nt < 4; nt++) {
                    uint32_t bb2[2] = {bc[nt], bc[4 + nt]};
                    mma_tf32(acc[mt][nt], a[mt], bb2);
                }
        }

        float bb[4][2];
#pragma unroll
        for (int nt = 0; nt < 4; nt++) {
            int d = nt * 8 + 2 * t;
            bb[nt][0] = bias[s * 128 + head * 32 + d];
            bb[nt][1] = bias[s * 128 + head * 32 + d + 1];
        }
#pragma unroll
        for (int mt = 0; mt < 4; mt++)
#pragma unroll
            for (int h = 0; h < 2; h++) {
                int idx = mt * 2 + h;
                size_t dst0 = ((size_t)(s * 16384 + whbase[idx]) * 49 + lwin8[idx]) * 32;
#pragma unroll
                for (int nt = 0; nt < 4; nt++) {
                    int d = nt * 8 + 2 * t;
                    float2 v = make_float2(acc[mt][nt][2 * h]     + bb[nt][0],
                                           acc[mt][nt][2 * h + 1] + bb[nt][1]);
                    *(float2*)&g_qkv[dst0 + d] = v;
                }
            }
    }
}

// ---------------------------------------------------------------------------
// Kernel 3: projection GEMM. Same core, distance-1 W prefetch.
// ---------------------------------------------------------------------------
__global__ __launch_bounds__(256, 2) void proj_gemm_mma(
    const float* __restrict__ W, const float* __restrict__ bias,
    float* __restrict__ out)
{
    extern __shared__ uint32_t As[];

    int tid = threadIdx.x, bm = blockIdx.x;
    int lane = tid & 31, warp = tid >> 5;
    int g = lane >> 2, t = lane & 3;
    int m0 = (warp >> 2) * 64, n0 = (warp & 3) * 32;

    {
        const float4* Ap = (const float4*)(g_att + (size_t)bm * 128 * 128);
        for (int i = tid; i < 4096; i += 256) {
            int r = i >> 5, c = (i & 31) << 2;
            float4 v = Ap[i];
            uint4 u = make_uint4(f2tf32(v.x), f2tf32(v.y), f2tf32(v.z), f2tf32(v.w));
            *(uint4*)&As[r * A_STR + c] = u;
        }
    }
    __syncthreads();

    const float* Wp = W + n0 + g;
    float acc[4][4][4] = {};
    uint32_t bv[8];
    {
        const float* w0 = Wp + (size_t)t * 128;
        const float* w1 = w0 + 4 * 128;
#pragma unroll
        for (int nt = 0; nt < 4; nt++) {
            bv[nt]     = f2tf32(__ldg(w0 + nt * 8));
            bv[4 + nt] = f2tf32(__ldg(w1 + nt * 8));
        }
    }
#pragma unroll
    for (int k0 = 0; k0 < 128; k0 += 8) {
        uint32_t bc[8];
#pragma unroll
        for (int j = 0; j < 8; j++) bc[j] = bv[j];
        if (k0 < 120) {
            const float* w0 = Wp + (size_t)(k0 + 8 + t) * 128;
            const float* w1 = w0 + 4 * 128;
#pragma unroll
            for (int nt = 0; nt < 4; nt++) {
                bv[nt]     = f2tf32(__ldg(w0 + nt * 8));
                bv[4 + nt] = f2tf32(__ldg(w1 + nt * 8));
            }
        }
        uint32_t a[4][4];
#pragma unroll
        for (int mt = 0; mt < 4; mt++) {
            int base = (m0 + mt * 16 + g) * A_STR + k0 + t;
            a[mt][0] = As[base];
            a[mt][1] = As[base + 8 * A_STR];
            a[mt][2] = As[base + 4];
            a[mt][3] = As[base + 8 * A_STR + 4];
        }
#pragma unroll
        for (int mt = 0; mt < 4; mt++)
#pragma unroll
            for (int nt = 0; nt < 4; nt++) {
                uint32_t bb2[2] = {bc[nt], bc[4 + nt]};
                mma_tf32(acc[mt][nt], a[mt], bb2);
            }
    }

    float bb[4][2];
#pragma unroll
    for (int nt = 0; nt < 4; nt++) {
        int d = n0 + nt * 8 + 2 * t;
        bb[nt][0] = bias[d];
        bb[nt][1] = bias[d + 1];
    }
#pragma unroll
    for (int mt = 0; mt < 4; mt++)
#pragma unroll
        for (int h = 0; h < 2; h++) {
            int r = m0 + mt * 16 + g + h * 8;
            float* op = out + ((size_t)bm * 128 + r) * 128;
#pragma unroll
            for (int nt = 0; nt < 4; nt++) {
                int d = n0 + nt * 8 + 2 * t;
                float2 v = make_float2(acc[mt][nt][2 * h]     + bb[nt][0],
                                       acc[mt][nt][2 * h + 1] + bb[nt][1]);
                *(float2*)&op[d] = v;
            }
        }
}

// ---------------------------------------------------------------------------
// Kernel 2: attention via mma.sync tf32. One block per (window, head),
// 128 threads. S epilogue reads precomputed g_comb (single load).
// ---------------------------------------------------------------------------
__global__ __launch_bounds__(128) void attn_mma()
{
    __shared__ uint32_t sQ [64 * 36];
    __shared__ uint32_t sKT[32 * 72];
    __shared__ uint32_t sV [64 * 40];
    __shared__ float    sS [64 * 72];

    int tid  = threadIdx.x;
    int lane = tid & 31, warp = tid >> 5;
    int g = lane >> 2, t = lane & 3;
    int wh   = blockIdx.x;
    int head = wh & 3;
    int widx = wh >> 2;
    int bimg = widx >> 6;
    int win  = widx & 63;
    const float* qp = g_qkv + (size_t)wh * 1568;
    const float* kp = g_qkv + (size_t)(16384 + wh) * 1568;
    const float* vp = g_qkv + (size_t)(2 * 16384 + wh) * 1568;
    const float* combp = g_comb + (size_t)(win * 4 + head) * 2401;

    for (int idx = tid; idx < 512; idx += 128) {
        int l = idx >> 3, c4 = (idx & 7) << 2;
        float4 q4 = make_float4(0.f, 0.f, 0.f, 0.f), k4 = q4, v4 = q4;
        if (l < 49) {
            q4 = *(const float4*)(qp + l * 32 + c4);
            k4 = *(const float4*)(kp + l * 32 + c4);
            v4 = *(const float4*)(vp + l * 32 + c4);
        }
        *(uint4*)&sQ[l * 36 + c4] = make_uint4(f2tf32(q4.x), f2tf32(q4.y), f2tf32(q4.z), f2tf32(q4.w));
        sKT[(c4 + 0) * 72 + l] = f2tf32(k4.x);
        sKT[(c4 + 1) * 72 + l] = f2tf32(k4.y);
        sKT[(c4 + 2) * 72 + l] = f2tf32(k4.z);
        sKT[(c4 + 3) * 72 + l] = f2tf32(k4.w);
        *(uint4*)&sV[l * 40 + c4] = make_uint4(f2tf32(v4.x), f2tf32(v4.y), f2tf32(v4.z), f2tf32(v4.w));
    }
    __syncthreads();

    int m0 = warp * 16;

    // ---- S strip (16 x 64) per warp ----
    {
        float acc[8][4] = {};
#pragma unroll
        for (int k0 = 0; k0 < 32; k0 += 8) {
            uint32_t a[4];
            int ab = (m0 + g) * 36 + k0 + t;
            a[0] = sQ[ab];
            a[1] = sQ[ab + 8 * 36];
            a[2] = sQ[ab + 4];
            a[3] = sQ[ab + 8 * 36 + 4];
#pragma unroll
            for (int nt = 0; nt < 8; nt++) {
                uint32_t b[2];
                int bb = (k0 + t) * 72 + nt * 8 + g;
                b[0] = sKT[bb];
                b[1] = sKT[bb + 4 * 72];
                mma_tf32(acc[nt], a, b);
            }
        }
        const float scale = 0.17677669529663687f;
#pragma unroll
        for (int h = 0; h < 2; h++) {
            int i = m0 + g + h * 8;
            if (i < 49) {
#pragma unroll
                for (int nt = 0; nt < 8; nt++) {
#pragma unroll
                    for (int e = 0; e < 2; e++) {
                        int j = nt * 8 + 2 * t + e;
                        float val = -1e30f;
                        if (j < 49)
                            val = acc[nt][2 * h + e] * scale + __ldg(combp + i * 49 + j);
                        sS[i * 72 + j] = val;
                    }
                }
            }
        }
    }
    __syncthreads();

    // ---- softmax (2 threads per row), write back tf32 bits ----
    {
        uint32_t* sSu = (uint32_t*)sS;
        int row = tid >> 1, q = tid & 1;
        bool valid = row < 49;
        float mx = -1e30f;
        if (valid)
            for (int j = q; j < 64; j += 2) mx = fmaxf(mx, sS[row * 72 + j]);
        mx = fmaxf(mx, __shfl_xor_sync(0xffffffffu, mx, 1));
        float sum = 0.f;
        if (valid)
            for (int j = q; j < 64; j += 2) {
                float e = __expf(sS[row * 72 + j] - mx);
                sS[row * 72 + j] = e;
                sum += e;
            }
        sum += __shfl_xor_sync(0xffffffffu, sum, 1);
        float inv = 1.f / sum;
        for (int j = q; j < 64; j += 2)
            sSu[row * 72 + j] = valid ? f2tf32(sS[row * 72 + j] * inv) : 0u;
    }
    __syncthreads();

    // ---- O strip (16 x 32) per warp ----
    {
        const uint32_t* sSu = (const uint32_t*)sS;
        float oac[4][4] = {};
#pragma unroll
        for (int k0 = 0; k0 < 64; k0 += 8) {
            uint32_t a[4];
            int ab = (m0 + g) * 72 + k0 + t;
            a[0] = sSu[ab];
            a[1] = sSu[ab + 8 * 72];
            a[2] = sSu[ab + 4];
            a[3] = sSu[ab + 8 * 72 + 4];
#pragma unroll
            for (int nt = 0; nt < 4; nt++) {
                uint32_t b[2];
                int bb = (k0 + t) * 40 + nt * 8 + g;
                b[0] = sV[bb];
                b[1] = sV[bb + 4 * 40];
                mma_tf32(oac[nt], a, b);
            }
        }
        int ybase = (win >> 3) * 7;
        int xbase = (win & 7) * 7;
#pragma unroll
        for (int h = 0; h < 2; h++) {
            int i = m0 + g + h * 8;
            if (i < 49) {
                int wy = i / 7, wx = i - wy * 7;
                float* op = g_att + (((size_t)(bimg * 56 + ybase + wy)) * 56 + (xbase + wx)) * 128
                          + head * 32;
#pragma unroll
                for (int nt = 0; nt < 4; nt++)
                    *(float2*)&op[nt * 8 + 2 * t] =
                        make_float2(oac[nt][2 * h], oac[nt][2 * h + 1]);
            }
        }
    }
}

// ---------------------------------------------------------------------------
extern "C" void kernel_launch(void* const* d_in, const int* in_sizes, int n_in,
                              void* d_out, int out_size)
{
    const float* x      = nullptr;
    const int*   relidx = nullptr;
    const float* mask   = nullptr;
    const float* qkv_w  = nullptr;
    const float* qkv_b  = nullptr;
    const float* relt   = nullptr;
    const float* proj_w = nullptr;
    const float* proj_b = nullptr;

    for (int i = 0; i < n_in; i++) {
        switch (in_sizes[i]) {
            case 25690112: x      = (const float*)d_in[i]; break;
            case 2401:     relidx = (const int*)  d_in[i]; break;
            case 153664:   mask   = (const float*)d_in[i]; break;
            case 49152:    qkv_w  = (const float*)d_in[i]; break;
            case 384:      qkv_b  = (const float*)d_in[i]; break;
            case 676:      relt   = (const float*)d_in[i]; break;
            case 16384:    proj_w = (const float*)d_in[i]; break;
            case 128:      proj_b = (const float*)d_in[i]; break;
            default: break;
        }
    }

    cudaFuncSetAttribute(qkv_gemm_mma,  cudaFuncAttributeMaxDynamicSharedMemorySize, SM_A_BYTES);
    cudaFuncSetAttribute(proj_gemm_mma, cudaFuncAttributeMaxDynamicSharedMemorySize, SM_A_BYTES);

    combine_bias<<<(COMB_ELEMS + 255) / 256, 256>>>(relidx, mask, relt);

    qkv_gemm_mma<<<TOKENS / 128, 256, SM_A_BYTES>>>(x, qkv_w, qkv_b);

    attn_mma<<<WH_TOTAL, 128>>>();

    proj_gemm_mma<<<TOKENS / 128, 256, SM_A_BYTES>>>(proj_w, proj_b, (float*)d_out);
}

// round 10
// speedup vs baseline: 1.2754x; 1.0355x over previous
#include <cuda_runtime.h>
#include <cuda_bf16.h>
#include <cstdint>

// Swin window attention. R10 = R9 resubmit (infra flake):
//  - K stored row-major (B-frag gathered, no transpose, no 8-way-conflict stores)
//  - g_qkv / g_att hold pre-truncated tf32 bits (attn & proj loads are raw copies)
// B=64, H=W=56, C=128, heads=4, hd=32, ws=7, L=49.

#define TOKENS   200704
#define WH_TOTAL 16384
#define QKV_ELEMS (3ull * 16384ull * 49ull * 32ull)
#define ATT_ELEMS ((size_t)TOKENS * 128)
#define COMB_ELEMS (64 * 4 * 2401)   // [win][head][ij]

__device__ float g_qkv[QKV_ELEMS];   // tf32 bits: [(s*16384 + wh)*49 + l]*32 + d
__device__ float g_att[ATT_ELEMS];   // tf32 bits: [b,h,w,c] pre-projection
__device__ float g_comb[COMB_ELEMS]; // relt[relidx[ij]][head] + mask[win][ij]

// ---------------------------------------------------------------------------
__device__ __forceinline__ uint32_t f2tf32(float x) {
    uint32_t r;
    asm("cvt.rna.tf32.f32 %0, %1;" : "=r"(r) : "f"(x));
    return r;
}
__device__ __forceinline__ void mma_tf32(float (&d)[4], const uint32_t* a, const uint32_t* b) {
    asm volatile("mma.sync.aligned.m16n8k8.row.col.f32.tf32.tf32.f32 "
                 "{%0,%1,%2,%3}, {%4,%5,%6,%7}, {%8,%9}, {%0,%1,%2,%3};"
                 : "+f"(d[0]), "+f"(d[1]), "+f"(d[2]), "+f"(d[3])
                 : "r"(a[0]), "r"(a[1]), "r"(a[2]), "r"(a[3]), "r"(b[0]), "r"(b[1]));
}

#define A_STR 132   // GEMM A smem stride (frag bank = 4g+t, conflict-free)
#define SM_A_BYTES (128 * A_STR * 4)   // 67584

// ---------------------------------------------------------------------------
// Kernel 0: combine relative-position bias and window mask.
// ---------------------------------------------------------------------------
__global__ __launch_bounds__(256) void combine_bias(
    const int* __restrict__ relidx, const float* __restrict__ mask,
    const float* __restrict__ relt)
{
    int i = blockIdx.x * 256 + threadIdx.x;
    if (i < COMB_ELEMS) {
        int ij = i % 2401;
        int wh = i / 2401;
        int head = wh & 3, win = wh >> 2;
        g_comb[i] = __ldg(relt + __ldg(relidx + ij) * 4 + head)
                  + __ldg(mask + (size_t)win * 2401 + ij);
    }
}

// ---------------------------------------------------------------------------
// Kernel 1: QKV GEMM. grid=1568, 256 threads (8 warps: 2m x 4n). A in smem,
// W fragments distance-1 pipelined from gmem. Epilogue stores tf32 bits.
// ---------------------------------------------------------------------------
__global__ __launch_bounds__(256, 2) void qkv_gemm_mma(
    const float* __restrict__ A, const float* __restrict__ W,
    const float* __restrict__ bias)
{
    extern __shared__ uint32_t As[];

    int tid = threadIdx.x, bm = blockIdx.x;
    int lane = tid & 31, warp = tid >> 5;
    int g = lane >> 2, t = lane & 3;
    int m0 = (warp >> 2) * 64, n0 = (warp & 3) * 32;
    int head = warp & 3;

    {
        const float4* Ap = (const float4*)(A + (size_t)bm * 128 * 128);
        for (int i = tid; i < 4096; i += 256) {
            int r = i >> 5, c = (i & 31) << 2;
            float4 v = Ap[i];
            uint4 u = make_uint4(f2tf32(v.x), f2tf32(v.y), f2tf32(v.z), f2tf32(v.w));
            *(uint4*)&As[r * A_STR + c] = u;
        }
    }

    int whbase[8], lwin8[8];
#pragma unroll
    for (int mt = 0; mt < 4; mt++)
#pragma unroll
        for (int h = 0; h < 2; h++) {
            int m = bm * 128 + m0 + mt * 16 + g + h * 8;
            int bimg = m / 3136;
            int rem  = m - bimg * 3136;
            int y = rem / 56, xx = rem - y * 56;
            int nhi = y / 7,  wy = y - nhi * 7;
            int nwi = xx / 7, wx = xx - nwi * 7;
            whbase[mt * 2 + h] = (bimg * 64 + nhi * 8 + nwi) * 4 + head;
            lwin8[mt * 2 + h]  = wy * 7 + wx;
        }
    __syncthreads();

#pragma unroll 1
    for (int s = 0; s < 3; s++) {
        const float* Wp = W + s * 128 + n0 + g;
        float acc[4][4][4] = {};

        uint32_t bv[8];
        {
            const float* w0 = Wp + (size_t)t * 384;
            const float* w1 = w0 + 4 * 384;
#pragma unroll
            for (int nt = 0; nt < 4; nt++) {
                bv[nt]     = f2tf32(__ldg(w0 + nt * 8));
                bv[4 + nt] = f2tf32(__ldg(w1 + nt * 8));
            }
        }
#pragma unroll
        for (int k0 = 0; k0 < 128; k0 += 8) {
            uint32_t bc[8];
#pragma unroll
            for (int j = 0; j < 8; j++) bc[j] = bv[j];
            if (k0 < 120) {
                const float* w0 = Wp + (size_t)(k0 + 8 + t) * 384;
                const float* w1 = w0 + 4 * 384;
#pragma unroll
                for (int nt = 0; nt < 4; nt++) {
                    bv[nt]     = f2tf32(__ldg(w0 + nt * 8));
                    bv[4 + nt] = f2tf32(__ldg(w1 + nt * 8));
                }
            }
            uint32_t a[4][4];
#pragma unroll
            for (int mt = 0; mt < 4; mt++) {
                int base = (m0 + mt * 16 + g) * A_STR + k0 + t;
                a[mt][0] = As[base];
                a[mt][1] = As[base + 8 * A_STR];
                a[mt][2] = As[base + 4];
                a[mt][3] = As[base + 8 * A_STR + 4];
            }
#pragma unroll
            for (int mt = 0; mt < 4; mt++)
#pragma unroll
                for (int nt = 0; nt < 4; nt++) {
                    uint32_t bb2[2] = {bc[nt], bc[4 + nt]};
                    mma_tf32(acc[mt][nt], a[mt], bb2);
                }
        }

        float bb[4][2];
#pragma unroll
        for (int nt = 0; nt < 4; nt++) {
            int d = nt * 8 + 2 * t;
            bb[nt][0] = bias[s * 128 + head * 32 + d];
            bb[nt][1] = bias[s * 128 + head * 32 + d + 1];
        }
#pragma unroll
        for (int mt = 0; mt < 4; mt++)
#pragma unroll
            for (int h = 0; h < 2; h++) {
                int idx = mt * 2 + h;
                size_t dst0 = ((size_t)(s * 16384 + whbase[idx]) * 49 + lwin8[idx]) * 32;
#pragma unroll
                for (int nt = 0; nt < 4; nt++) {
                    int d = nt * 8 + 2 * t;
                    uint2 v = make_uint2(f2tf32(acc[mt][nt][2 * h]     + bb[nt][0]),
                                         f2tf32(acc[mt][nt][2 * h + 1] + bb[nt][1]));
                    *(uint2*)&g_qkv[dst0 + d] = v;
                }
            }
    }
}

// ---------------------------------------------------------------------------
// Kernel 3: projection GEMM. A (g_att) already holds tf32 bits -> raw copy.
// ---------------------------------------------------------------------------
__global__ __launch_bounds__(256, 2) void proj_gemm_mma(
    const float* __restrict__ W, const float* __restrict__ bias,
    float* __restrict__ out)
{
    extern __shared__ uint32_t As[];

    int tid = threadIdx.x, bm = blockIdx.x;
    int lane = tid & 31, warp = tid >> 5;
    int g = lane >> 2, t = lane & 3;
    int m0 = (warp >> 2) * 64, n0 = (warp & 3) * 32;

    {
        const uint4* Ap = (const uint4*)(g_att + (size_t)bm * 128 * 128);
        for (int i = tid; i < 4096; i += 256) {
            int r = i >> 5, c = (i & 31) << 2;
            *(uint4*)&As[r * A_STR + c] = Ap[i];
        }
    }
    __syncthreads();

    const float* Wp = W + n0 + g;
    float acc[4][4][4] = {};
    uint32_t bv[8];
    {
        const float* w0 = Wp + (size_t)t * 128;
        const float* w1 = w0 + 4 * 128;
#pragma unroll
        for (int nt = 0; nt < 4; nt++) {
            bv[nt]     = f2tf32(__ldg(w0 + nt * 8));
            bv[4 + nt] = f2tf32(__ldg(w1 + nt * 8));
        }
    }
#pragma unroll
    for (int k0 = 0; k0 < 128; k0 += 8) {
        uint32_t bc[8];
#pragma unroll
        for (int j = 0; j < 8; j++) bc[j] = bv[j];
        if (k0 < 120) {
            const float* w0 = Wp + (size_t)(k0 + 8 + t) * 128;
            const float* w1 = w0 + 4 * 128;
#pragma unroll
            for (int nt = 0; nt < 4; nt++) {
                bv[nt]     = f2tf32(__ldg(w0 + nt * 8));
                bv[4 + nt] = f2tf32(__ldg(w1 + nt * 8));
            }
        }
        uint32_t a[4][4];
#pragma unroll
        for (int mt = 0; mt < 4; mt++) {
            int base = (m0 + mt * 16 + g) * A_STR + k0 + t;
            a[mt][0] = As[base];
            a[mt][1] = As[base + 8 * A_STR];
            a[mt][2] = As[base + 4];
            a[mt][3] = As[base + 8 * A_STR + 4];
        }
#pragma unroll
        for (int mt = 0; mt < 4; mt++)
#pragma unroll
            for (int nt = 0; nt < 4; nt++) {
                uint32_t bb2[2] = {bc[nt], bc[4 + nt]};
                mma_tf32(acc[mt][nt], a[mt], bb2);
            }
    }

    float bb[4][2];
#pragma unroll
    for (int nt = 0; nt < 4; nt++) {
        int d = n0 + nt * 8 + 2 * t;
        bb[nt][0] = bias[d];
        bb[nt][1] = bias[d + 1];
    }
#pragma unroll
    for (int mt = 0; mt < 4; mt++)
#pragma unroll
        for (int h = 0; h < 2; h++) {
            int r = m0 + mt * 16 + g + h * 8;
            float* op = out + ((size_t)bm * 128 + r) * 128;
#pragma unroll
            for (int nt = 0; nt < 4; nt++) {
                int d = n0 + nt * 8 + 2 * t;
                float2 v = make_float2(acc[mt][nt][2 * h]     + bb[nt][0],
                                       acc[mt][nt][2 * h + 1] + bb[nt][1]);
                *(float2*)&op[d] = v;
            }
        }
}

// ---------------------------------------------------------------------------
// Kernel 2: attention. One block per (window, head), 128 threads.
// Q/K stored [l][36], V [l][40]; B-fragments gathered (no transpose array).
// ---------------------------------------------------------------------------
__global__ __launch_bounds__(128) void attn_mma()
{
    __shared__ uint32_t sQ[64 * 36];   // tf32 Q [l][d], stride 36 (≡4 mod 32)
    __shared__ uint32_t sK[64 * 36];   // tf32 K [l][d], stride 36
    __shared__ uint32_t sV[64 * 40];   // tf32 V [l][d], stride 40 (≡8 mod 32)
    __shared__ float    sS[64 * 72];   // S / P, stride 72 (≡8 mod 32)

    int tid  = threadIdx.x;
    int lane = tid & 31, warp = tid >> 5;
    int g = lane >> 2, t = lane & 3;
    int wh   = blockIdx.x;
    int head = wh & 3;
    int widx = wh >> 2;
    int bimg = widx >> 6;
    int win  = widx & 63;
    const uint4* qp = (const uint4*)(g_qkv + (size_t)wh * 1568);
    const uint4* kp = (const uint4*)(g_qkv + (size_t)(16384 + wh) * 1568);
    const uint4* vp = (const uint4*)(g_qkv + (size_t)(2 * 16384 + wh) * 1568);
    const float* combp = g_comb + (size_t)(win * 4 + head) * 2401;

    // Load q/k/v (raw tf32 bits), rows l>=49 zero
    for (int idx = tid; idx < 512; idx += 128) {
        int l = idx >> 3, c4 = (idx & 7) << 2;
        uint4 z = make_uint4(0u, 0u, 0u, 0u);
        uint4 q4 = z, k4 = z, v4 = z;
        if (l < 49) {
            int e = (l * 32 + c4) >> 2;
            q4 = qp[e]; k4 = kp[e]; v4 = vp[e];
        }
        *(uint4*)&sQ[l * 36 + c4] = q4;
        *(uint4*)&sK[l * 36 + c4] = k4;
        *(uint4*)&sV[l * 40 + c4] = v4;
    }
    __syncthreads();

    int m0 = warp * 16;

    // ---- S strip (16 x 64) per warp ----
    {
        float acc[8][4] = {};
#pragma unroll
        for (int k0 = 0; k0 < 32; k0 += 8) {
            uint32_t a[4];
            int ab = (m0 + g) * 36 + k0 + t;
            a[0] = sQ[ab];
            a[1] = sQ[ab + 8 * 36];
            a[2] = sQ[ab + 4];
            a[3] = sQ[ab + 8 * 36 + 4];
#pragma unroll
            for (int nt = 0; nt < 8; nt++) {
                uint32_t b[2];
                int bb = (nt * 8 + g) * 36 + k0 + t;   // K[n][k] gather, bank 4g+t
                b[0] = sK[bb];
                b[1] = sK[bb + 4];
                mma_tf32(acc[nt], a, b);
            }
        }
        const float scale = 0.17677669529663687f;
#pragma unroll
        for (int h = 0; h < 2; h++) {
            int i = m0 + g + h * 8;
            if (i < 49) {
#pragma unroll
                for (int nt = 0; nt < 8; nt++) {
#pragma unroll
                    for (int e = 0; e < 2; e++) {
                        int j = nt * 8 + 2 * t + e;
                        float val = -1e30f;
                        if (j < 49)
                            val = acc[nt][2 * h + e] * scale + __ldg(combp + i * 49 + j);
                        sS[i * 72 + j] = val;
                    }
                }
            }
        }
    }
    __syncthreads();

    // ---- softmax (2 threads per row), write back tf32 bits ----
    {
        uint32_t* sSu = (uint32_t*)sS;
        int row = tid >> 1, q = tid & 1;
        bool valid = row < 49;
        float mx = -1e30f;
        if (valid)
            for (int j = q; j < 64; j += 2) mx = fmaxf(mx, sS[row * 72 + j]);
        mx = fmaxf(mx, __shfl_xor_sync(0xffffffffu, mx, 1));
        float sum = 0.f;
        if (valid)
            for (int j = q; j < 64; j += 2) {
                float e = __expf(sS[row * 72 + j] - mx);
                sS[row * 72 + j] = e;
                sum += e;
            }
        sum += __shfl_xor_sync(0xffffffffu, sum, 1);
        float inv = 1.f / sum;
        for (int j = q; j < 64; j += 2)
            sSu[row * 72 + j] = valid ? f2tf32(sS[row * 72 + j] * inv) : 0u;
    }
    __syncthreads();

    // ---- O strip (16 x 32) per warp, store tf32 bits to g_att ----
    {
        const uint32_t* sSu = (const uint32_t*)sS;
        float oac[4][4] = {};
#pragma unroll
        for (int k0 = 0; k0 < 64; k0 += 8) {
            uint32_t a[4];
            int ab = (m0 + g) * 72 + k0 + t;
            a[0] = sSu[ab];
            a[1] = sSu[ab + 8 * 72];
            a[2] = sSu[ab + 4];
            a[3] = sSu[ab + 8 * 72 + 4];
#pragma unroll
            for (int nt = 0; nt < 4; nt++) {
                uint32_t b[2];
                int bb = (k0 + t) * 40 + nt * 8 + g;
                b[0] = sV[bb];
                b[1] = sV[bb + 4 * 40];
                mma_tf32(oac[nt], a, b);
            }
        }
        int ybase = (win >> 3) * 7;
        int xbase = (win & 7) * 7;
#pragma unroll
        for (int h = 0; h < 2; h++) {
            int i = m0 + g + h * 8;
            if (i < 49) {
                int wy = i / 7, wx = i - wy * 7;
                float* op = g_att + (((size_t)(bimg * 56 + ybase + wy)) * 56 + (xbase + wx)) * 128
                          + head * 32;
#pragma unroll
                for (int nt = 0; nt < 4; nt++) {
                    uint2 v = make_uint2(f2tf32(oac[nt][2 * h]),
                                         f2tf32(oac[nt][2 * h + 1]));
                    *(uint2*)&op[nt * 8 + 2 * t] = v;
                }
            }
        }
    }
}

// ---------------------------------------------------------------------------
extern "C" void kernel_launch(void* const* d_in, const int* in_sizes, int n_in,
                              void* d_out, int out_size)
{
    const float* x      = nullptr;
    const int*   relidx = nullptr;
    const float* mask   = nullptr;
    const float* qkv_w  = nullptr;
    const float* qkv_b  = nullptr;
    const float* relt   = nullptr;
    const float* proj_w = nullptr;
    const float* proj_b = nullptr;

    for (int i = 0; i < n_in; i++) {
        switch (in_sizes[i]) {
            case 25690112: x      = (const float*)d_in[i]; break;
            case 2401:     relidx = (const int*)  d_in[i]; break;
            case 153664:   mask   = (const float*)d_in[i]; break;
            case 49152:    qkv_w  = (const float*)d_in[i]; break;
            case 384:      qkv_b  = (const float*)d_in[i]; break;
            case 676:      relt   = (const float*)d_in[i]; break;
            case 16384:    proj_w = (const float*)d_in[i]; break;
            case 128:      proj_b = (const float*)d_in[i]; break;
            default: break;
        }
    }

    cudaFuncSetAttribute(qkv_gemm_mma,  cudaFuncAttributeMaxDynamicSharedMemorySize, SM_A_BYTES);
    cudaFuncSetAttribute(proj_gemm_mma, cudaFuncAttributeMaxDynamicSharedMemorySize, SM_A_BYTES);

    combine_bias<<<(COMB_ELEMS + 255) / 256, 256>>>(relidx, mask, relt);

    qkv_gemm_mma<<<TOKENS / 128, 256, SM_A_BYTES>>>(x, qkv_w, qkv_b);

    attn_mma<<<WH_TOTAL, 128>>>();

    proj_gemm_mma<<<TOKENS / 128, 256, SM_A_BYTES>>>(proj_w, proj_b, (float*)d_out);
}

// round 11
// speedup vs baseline: 1.5691x; 1.2303x over previous
#include <cuda_runtime.h>
#include <cuda_bf16.h>
#include <cstdint>

// Swin window attention. R11 = R10 + in-register softmax attention:
//  - softmax on QK^T accumulator fragments (shfl reduce), no S smem round-trip
//  - comb table prefetched to registers before the S MMA loop
//  - one __syncthreads per attn block (PV A-frag rows are warp-private -> __syncwarp)
// B=64, H=W=56, C=128, heads=4, hd=32, ws=7, L=49.

#define TOKENS   200704
#define WH_TOTAL 16384
#define QKV_ELEMS (3ull * 16384ull * 49ull * 32ull)
#define ATT_ELEMS ((size_t)TOKENS * 128)
#define COMB_ELEMS (64 * 4 * 2401)   // [win][head][ij]

__device__ float g_qkv[QKV_ELEMS];   // tf32 bits: [(s*16384 + wh)*49 + l]*32 + d
__device__ float g_att[ATT_ELEMS];   // tf32 bits: [b,h,w,c] pre-projection
__device__ float g_comb[COMB_ELEMS]; // relt[relidx[ij]][head] + mask[win][ij]

// ---------------------------------------------------------------------------
__device__ __forceinline__ uint32_t f2tf32(float x) {
    uint32_t r;
    asm("cvt.rna.tf32.f32 %0, %1;" : "=r"(r) : "f"(x));
    return r;
}
__device__ __forceinline__ void mma_tf32(float (&d)[4], const uint32_t* a, const uint32_t* b) {
    asm volatile("mma.sync.aligned.m16n8k8.row.col.f32.tf32.tf32.f32 "
                 "{%0,%1,%2,%3}, {%4,%5,%6,%7}, {%8,%9}, {%0,%1,%2,%3};"
                 : "+f"(d[0]), "+f"(d[1]), "+f"(d[2]), "+f"(d[3])
                 : "r"(a[0]), "r"(a[1]), "r"(a[2]), "r"(a[3]), "r"(b[0]), "r"(b[1]));
}

#define A_STR 132   // GEMM A smem stride (frag bank = 4g+t, conflict-free)
#define SM_A_BYTES (128 * A_STR * 4)   // 67584

// ---------------------------------------------------------------------------
// Kernel 0: combine relative-position bias and window mask.
// ---------------------------------------------------------------------------
__global__ __launch_bounds__(256) void combine_bias(
    const int* __restrict__ relidx, const float* __restrict__ mask,
    const float* __restrict__ relt)
{
    int i = blockIdx.x * 256 + threadIdx.x;
    if (i < COMB_ELEMS) {
        int ij = i % 2401;
        int wh = i / 2401;
        int head = wh & 3, win = wh >> 2;
        g_comb[i] = __ldg(relt + __ldg(relidx + ij) * 4 + head)
                  + __ldg(mask + (size_t)win * 2401 + ij);
    }
}

// ---------------------------------------------------------------------------
// Kernel 1: QKV GEMM. grid=1568, 256 threads (8 warps: 2m x 4n). A in smem,
// W fragments distance-1 pipelined from gmem. Epilogue stores tf32 bits.
// ---------------------------------------------------------------------------
__global__ __launch_bounds__(256, 2) void qkv_gemm_mma(
    const float* __restrict__ A, const float* __restrict__ W,
    const float* __restrict__ bias)
{
    extern __shared__ uint32_t As[];

    int tid = threadIdx.x, bm = blockIdx.x;
    int lane = tid & 31, warp = tid >> 5;
    int g = lane >> 2, t = lane & 3;
    int m0 = (warp >> 2) * 64, n0 = (warp & 3) * 32;
    int head = warp & 3;

    {
        const float4* Ap = (const float4*)(A + (size_t)bm * 128 * 128);
        for (int i = tid; i < 4096; i += 256) {
            int r = i >> 5, c = (i & 31) << 2;
            float4 v = Ap[i];
            uint4 u = make_uint4(f2tf32(v.x), f2tf32(v.y), f2tf32(v.z), f2tf32(v.w));
            *(uint4*)&As[r * A_STR + c] = u;
        }
    }

    int whbase[8], lwin8[8];
#pragma unroll
    for (int mt = 0; mt < 4; mt++)
#pragma unroll
        for (int h = 0; h < 2; h++) {
            int m = bm * 128 + m0 + mt * 16 + g + h * 8;
            int bimg = m / 3136;
            int rem  = m - bimg * 3136;
            int y = rem / 56, xx = rem - y * 56;
            int nhi = y / 7,  wy = y - nhi * 7;
            int nwi = xx / 7, wx = xx - nwi * 7;
            whbase[mt * 2 + h] = (bimg * 64 + nhi * 8 + nwi) * 4 + head;
            lwin8[mt * 2 + h]  = wy * 7 + wx;
        }
    __syncthreads();

#pragma unroll 1
    for (int s = 0; s < 3; s++) {
        const float* Wp = W + s * 128 + n0 + g;
        float acc[4][4][4] = {};

        uint32_t bv[8];
        {
            const float* w0 = Wp + (size_t)t * 384;
            const float* w1 = w0 + 4 * 384;
#pragma unroll
            for (int nt = 0; nt < 4; nt++) {
                bv[nt]     = f2tf32(__ldg(w0 + nt * 8));
                bv[4 + nt] = f2tf32(__ldg(w1 + nt * 8));
            }
        }
#pragma unroll
        for (int k0 = 0; k0 < 128; k0 += 8) {
            uint32_t bc[8];
#pragma unroll
            for (int j = 0; j < 8; j++) bc[j] = bv[j];
            if (k0 < 120) {
                const float* w0 = Wp + (size_t)(k0 + 8 + t) * 384;
                const float* w1 = w0 + 4 * 384;
#pragma unroll
                for (int nt = 0; nt < 4; nt++) {
                    bv[nt]     = f2tf32(__ldg(w0 + nt * 8));
                    bv[4 + nt] = f2tf32(__ldg(w1 + nt * 8));
                }
            }
            uint32_t a[4][4];
#pragma unroll
            for (int mt = 0; mt < 4; mt++) {
                int base = (m0 + mt * 16 + g) * A_STR + k0 + t;
                a[mt][0] = As[base];
                a[mt][1] = As[base + 8 * A_STR];
                a[mt][2] = As[base + 4];
                a[mt][3] = As[base + 8 * A_STR + 4];
            }
#pragma unroll
            for (int mt = 0; mt < 4; mt++)
#pragma unroll
                for (int nt = 0; nt < 4; nt++) {
                    uint32_t bb2[2] = {bc[nt], bc[4 + nt]};
                    mma_tf32(acc[mt][nt], a[mt], bb2);
                }
        }

        float bb[4][2];
#pragma unroll
        for (int nt = 0; nt < 4; nt++) {
            int d = nt * 8 + 2 * t;
            bb[nt][0] = bias[s * 128 + head * 32 + d];
            bb[nt][1] = bias[s * 128 + head * 32 + d + 1];
        }
#pragma unroll
        for (int mt = 0; mt < 4; mt++)
#pragma unroll
            for (int h = 0; h < 2; h++) {
                int idx = mt * 2 + h;
                size_t dst0 = ((size_t)(s * 16384 + whbase[idx]) * 49 + lwin8[idx]) * 32;
#pragma unroll
                for (int nt = 0; nt < 4; nt++) {
                    int d = nt * 8 + 2 * t;
                    uint2 v = make_uint2(f2tf32(acc[mt][nt][2 * h]     + bb[nt][0]),
                                         f2tf32(acc[mt][nt][2 * h + 1] + bb[nt][1]));
                    *(uint2*)&g_qkv[dst0 + d] = v;
                }
            }
    }
}

// ---------------------------------------------------------------------------
// Kernel 3: projection GEMM. A (g_att) already holds tf32 bits -> raw copy.
// ---------------------------------------------------------------------------
__global__ __launch_bounds__(256, 2) void proj_gemm_mma(
    const float* __restrict__ W, const float* __restrict__ bias,
    float* __restrict__ out)
{
    extern __shared__ uint32_t As[];

    int tid = threadIdx.x, bm = blockIdx.x;
    int lane = tid & 31, warp = tid >> 5;
    int g = lane >> 2, t = lane & 3;
    int m0 = (warp >> 2) * 64, n0 = (warp & 3) * 32;

    {
        const uint4* Ap = (const uint4*)(g_att + (size_t)bm * 128 * 128);
        for (int i = tid; i < 4096; i += 256) {
            int r = i >> 5, c = (i & 31) << 2;
            *(uint4*)&As[r * A_STR + c] = Ap[i];
        }
    }
    __syncthreads();

    const float* Wp = W + n0 + g;
    float acc[4][4][4] = {};
    uint32_t bv[8];
    {
        const float* w0 = Wp + (size_t)t * 128;
        const float* w1 = w0 + 4 * 128;
#pragma unroll
        for (int nt = 0; nt < 4; nt++) {
            bv[nt]     = f2tf32(__ldg(w0 + nt * 8));
            bv[4 + nt] = f2tf32(__ldg(w1 + nt * 8));
        }
    }
#pragma unroll
    for (int k0 = 0; k0 < 128; k0 += 8) {
        uint32_t bc[8];
#pragma unroll
        for (int j = 0; j < 8; j++) bc[j] = bv[j];
        if (k0 < 120) {
            const float* w0 = Wp + (size_t)(k0 + 8 + t) * 128;
            const float* w1 = w0 + 4 * 128;
#pragma unroll
            for (int nt = 0; nt < 4; nt++) {
                bv[nt]     = f2tf32(__ldg(w0 + nt * 8));
                bv[4 + nt] = f2tf32(__ldg(w1 + nt * 8));
            }
        }
        uint32_t a[4][4];
#pragma unroll
        for (int mt = 0; mt < 4; mt++) {
            int base = (m0 + mt * 16 + g) * A_STR + k0 + t;
            a[mt][0] = As[base];
            a[mt][1] = As[base + 8 * A_STR];
            a[mt][2] = As[base + 4];
            a[mt][3] = As[base + 8 * A_STR + 4];
        }
#pragma unroll
        for (int mt = 0; mt < 4; mt++)
#pragma unroll
            for (int nt = 0; nt < 4; nt++) {
                uint32_t bb2[2] = {bc[nt], bc[4 + nt]};
                mma_tf32(acc[mt][nt], a[mt], bb2);
            }
    }

    float bb[4][2];
#pragma unroll
    for (int nt = 0; nt < 4; nt++) {
        int d = n0 + nt * 8 + 2 * t;
        bb[nt][0] = bias[d];
        bb[nt][1] = bias[d + 1];
    }
#pragma unroll
    for (int mt = 0; mt < 4; mt++)
#pragma unroll
        for (int h = 0; h < 2; h++) {
            int r = m0 + mt * 16 + g + h * 8;
            float* op = out + ((size_t)bm * 128 + r) * 128;
#pragma unroll
            for (int nt = 0; nt < 4; nt++) {
                int d = n0 + nt * 8 + 2 * t;
                float2 v = make_float2(acc[mt][nt][2 * h]     + bb[nt][0],
                                       acc[mt][nt][2 * h + 1] + bb[nt][1]);
                *(float2*)&op[d] = v;
            }
        }
}

// ---------------------------------------------------------------------------
// Kernel 2: attention. One block per (window, head), 128 threads.
// In-register softmax on the QK^T accumulator; single __syncthreads.
// ---------------------------------------------------------------------------
__global__ __launch_bounds__(128) void attn_mma()
{
    __shared__ uint32_t sQ[64 * 36];   // tf32 Q [l][d], stride 36 (≡4 mod 32)
    __shared__ uint32_t sK[64 * 36];   // tf32 K [l][d], stride 36
    __shared__ uint32_t sV[64 * 40];   // tf32 V [l][d], stride 40 (≡8 mod 32)
    __shared__ uint32_t sP[64 * 72];   // P tf32 bits, stride 72 (≡8 mod 32)

    int tid  = threadIdx.x;
    int lane = tid & 31, warp = tid >> 5;
    int g = lane >> 2, t = lane & 3;
    int wh   = blockIdx.x;
    int head = wh & 3;
    int widx = wh >> 2;
    int bimg = widx >> 6;
    int win  = widx & 63;
    const uint4* qp = (const uint4*)(g_qkv + (size_t)wh * 1568);
    const uint4* kp = (const uint4*)(g_qkv + (size_t)(16384 + wh) * 1568);
    const uint4* vp = (const uint4*)(g_qkv + (size_t)(2 * 16384 + wh) * 1568);
    const float* combp = g_comb + (size_t)(win * 4 + head) * 2401;

    // Load q/k/v (raw tf32 bits), rows l>=49 zero
    for (int idx = tid; idx < 512; idx += 128) {
        int l = idx >> 3, c4 = (idx & 7) << 2;
        uint4 z = make_uint4(0u, 0u, 0u, 0u);
        uint4 q4 = z, k4 = z, v4 = z;
        if (l < 49) {
            int e = (l * 32 + c4) >> 2;
            q4 = qp[e]; k4 = kp[e]; v4 = vp[e];
        }
        *(uint4*)&sQ[l * 36 + c4] = q4;
        *(uint4*)&sK[l * 36 + c4] = k4;
        *(uint4*)&sV[l * 40 + c4] = v4;
    }

    int m0 = warp * 16;

    // Prefetch comb values for this thread's 32 S elements (overlap with sync+mma)
    float cmb[8][4];   // [nt][2h+e]
#pragma unroll
    for (int h = 0; h < 2; h++) {
        int i = m0 + g + h * 8;
#pragma unroll
        for (int nt = 0; nt < 8; nt++)
#pragma unroll
            for (int e = 0; e < 2; e++) {
                int j = nt * 8 + 2 * t + e;
                cmb[nt][2 * h + e] = (i < 49 && j < 49)
                                   ? __ldg(combp + i * 49 + j) : -1e30f;
            }
    }
    __syncthreads();

    // ---- S strip (16 x 64) per warp ----
    float acc[8][4] = {};
#pragma unroll
    for (int k0 = 0; k0 < 32; k0 += 8) {
        uint32_t a[4];
        int ab = (m0 + g) * 36 + k0 + t;
        a[0] = sQ[ab];
        a[1] = sQ[ab + 8 * 36];
        a[2] = sQ[ab + 4];
        a[3] = sQ[ab + 8 * 36 + 4];
#pragma unroll
        for (int nt = 0; nt < 8; nt++) {
            uint32_t b[2];
            int bb = (nt * 8 + g) * 36 + k0 + t;   // K[n][k] gather, bank 4g+t
            b[0] = sK[bb];
            b[1] = sK[bb + 4];
            mma_tf32(acc[nt], a, b);
        }
    }

    // ---- in-register softmax (rows g, g+8 of the strip) ----
    {
        const float scale = 0.17677669529663687f;
        float mx2[2] = {-1e30f, -1e30f};
#pragma unroll
        for (int nt = 0; nt < 8; nt++)
#pragma unroll
            for (int he = 0; he < 4; he++) {
                float v = acc[nt][he] * scale + cmb[nt][he];
                acc[nt][he] = v;
                mx2[he >> 1] = fmaxf(mx2[he >> 1], v);
            }
#pragma unroll
        for (int h = 0; h < 2; h++) {
            mx2[h] = fmaxf(mx2[h], __shfl_xor_sync(0xffffffffu, mx2[h], 1));
            mx2[h] = fmaxf(mx2[h], __shfl_xor_sync(0xffffffffu, mx2[h], 2));
        }
        float sm2[2] = {0.f, 0.f};
#pragma unroll
        for (int nt = 0; nt < 8; nt++)
#pragma unroll
            for (int he = 0; he < 4; he++) {
                float p = __expf(acc[nt][he] - mx2[he >> 1]);
                acc[nt][he] = p;
                sm2[he >> 1] += p;
            }
#pragma unroll
        for (int h = 0; h < 2; h++) {
            sm2[h] += __shfl_xor_sync(0xffffffffu, sm2[h], 1);
            sm2[h] += __shfl_xor_sync(0xffffffffu, sm2[h], 2);
        }
        float inv0 = 1.f / sm2[0], inv1 = 1.f / sm2[1];
#pragma unroll
        for (int h = 0; h < 2; h++) {
            float inv = h ? inv1 : inv0;
            int row = m0 + g + h * 8;
#pragma unroll
            for (int nt = 0; nt < 8; nt++) {
                uint2 v = make_uint2(f2tf32(acc[nt][2 * h]     * inv),
                                     f2tf32(acc[nt][2 * h + 1] * inv));
                *(uint2*)&sP[row * 72 + nt * 8 + 2 * t] = v;
            }
        }
    }
    __syncwarp();   // PV A-frag rows are this warp's own strip

    // ---- O strip (16 x 32) per warp, store tf32 bits to g_att ----
    {
        float oac[4][4] = {};
#pragma unroll
        for (int k0 = 0; k0 < 64; k0 += 8) {
            uint32_t a[4];
            int ab = (m0 + g) * 72 + k0 + t;
            a[0] = sP[ab];
            a[1] = sP[ab + 8 * 72];
            a[2] = sP[ab + 4];
            a[3] = sP[ab + 8 * 72 + 4];
#pragma unroll
            for (int nt = 0; nt < 4; nt++) {
                uint32_t b[2];
                int bb = (k0 + t) * 40 + nt * 8 + g;
                b[0] = sV[bb];
                b[1] = sV[bb + 4 * 40];
                mma_tf32(oac[nt], a, b);
            }
        }
        int ybase = (win >> 3) * 7;
        int xbase = (win & 7) * 7;
#pragma unroll
        for (int h = 0; h < 2; h++) {
            int i = m0 + g + h * 8;
            if (i < 49) {
                int wy = i / 7, wx = i - wy * 7;
                float* op = g_att + (((size_t)(bimg * 56 + ybase + wy)) * 56 + (xbase + wx)) * 128
                          + head * 32;
#pragma unroll
                for (int nt = 0; nt < 4; nt++) {
                    uint2 v = make_uint2(f2tf32(oac[nt][2 * h]),
                                         f2tf32(oac[nt][2 * h + 1]));
                    *(uint2*)&op[nt * 8 + 2 * t] = v;
                }
            }
        }
    }
}

// ---------------------------------------------------------------------------
extern "C" void kernel_launch(void* const* d_in, const int* in_sizes, int n_in,
                              void* d_out, int out_size)
{
    const float* x      = nullptr;
    const int*   relidx = nullptr;
    const float* mask   = nullptr;
    const float* qkv_w  = nullptr;
    const float* qkv_b  = nullptr;
    const float* relt   = nullptr;
    const float* proj_w = nullptr;
    const float* proj_b = nullptr;

    for (int i = 0; i < n_in; i++) {
        switch (in_sizes[i]) {
            case 25690112: x      = (const float*)d_in[i]; break;
            case 2401:     relidx = (const int*)  d_in[i]; break;
            case 153664:   mask   = (const float*)d_in[i]; break;
            case 49152:    qkv_w  = (const float*)d_in[i]; break;
            case 384:      qkv_b  = (const float*)d_in[i]; break;
            case 676:      relt   = (const float*)d_in[i]; break;
            case 16384:    proj_w = (const float*)d_in[i]; break;
            case 128:      proj_b = (const float*)d_in[i]; break;
            default: break;
        }
    }

    cudaFuncSetAttribute(qkv_gemm_mma,  cudaFuncAttributeMaxDynamicSharedMemorySize, SM_A_BYTES);
    cudaFuncSetAttribute(proj_gemm_mma, cudaFuncAttributeMaxDynamicSharedMemorySize, SM_A_BYTES);

    combine_bias<<<(COMB_ELEMS + 255) / 256, 256>>>(relidx, mask, relt);

    qkv_gemm_mma<<<TOKENS / 128, 256, SM_A_BYTES>>>(x, qkv_w, qkv_b);

    attn_mma<<<WH_TOTAL, 128>>>();

    proj_gemm_mma<<<TOKENS / 128, 256, SM_A_BYTES>>>(proj_w, proj_b, (float*)d_out);
}

// round 13
// speedup vs baseline: 1.6270x; 1.0369x over previous
#include <cuda_runtime.h>
#include <cuda_bf16.h>
#include <cstdint>

// Swin window attention. R13 = R12 resubmit (infra flake), softmax store cleaned:
//  - sP aliased onto [sQ|sK] (dead after S-mma): smem 47 -> 28.7 KB
//  - comb prefetch moved after S-mma: peak regs down
//  -> attn CTAs/SM 4 -> ~6 (24 warps/SM)
// B=64, H=W=56, C=128, heads=4, hd=32, ws=7, L=49.

#define TOKENS   200704
#define WH_TOTAL 16384
#define QKV_ELEMS (3ull * 16384ull * 49ull * 32ull)
#define ATT_ELEMS ((size_t)TOKENS * 128)
#define COMB_ELEMS (64 * 4 * 2401)   // [win][head][ij]

__device__ float g_qkv[QKV_ELEMS];   // tf32 bits: [(s*16384 + wh)*49 + l]*32 + d
__device__ float g_att[ATT_ELEMS];   // tf32 bits: [b,h,w,c] pre-projection
__device__ float g_comb[COMB_ELEMS]; // relt[relidx[ij]][head] + mask[win][ij]

// ---------------------------------------------------------------------------
__device__ __forceinline__ uint32_t f2tf32(float x) {
    uint32_t r;
    asm("cvt.rna.tf32.f32 %0, %1;" : "=r"(r) : "f"(x));
    return r;
}
__device__ __forceinline__ void mma_tf32(float (&d)[4], const uint32_t* a, const uint32_t* b) {
    asm volatile("mma.sync.aligned.m16n8k8.row.col.f32.tf32.tf32.f32 "
                 "{%0,%1,%2,%3}, {%4,%5,%6,%7}, {%8,%9}, {%0,%1,%2,%3};"
                 : "+f"(d[0]), "+f"(d[1]), "+f"(d[2]), "+f"(d[3])
                 : "r"(a[0]), "r"(a[1]), "r"(a[2]), "r"(a[3]), "r"(b[0]), "r"(b[1]));
}

#define A_STR 132   // GEMM A smem stride (frag bank = 4g+t, conflict-free)
#define SM_A_BYTES (128 * A_STR * 4)   // 67584

// ---------------------------------------------------------------------------
// Kernel 0: combine relative-position bias and window mask.
// ---------------------------------------------------------------------------
__global__ __launch_bounds__(256) void combine_bias(
    const int* __restrict__ relidx, const float* __restrict__ mask,
    const float* __restrict__ relt)
{
    int i = blockIdx.x * 256 + threadIdx.x;
    if (i < COMB_ELEMS) {
        int ij = i % 2401;
        int wh = i / 2401;
        int head = wh & 3, win = wh >> 2;
        g_comb[i] = __ldg(relt + __ldg(relidx + ij) * 4 + head)
                  + __ldg(mask + (size_t)win * 2401 + ij);
    }
}

// ---------------------------------------------------------------------------
// Kernel 1: QKV GEMM. grid=1568, 256 threads (8 warps: 2m x 4n). A in smem,
// W fragments distance-1 pipelined from gmem. Epilogue stores tf32 bits.
// ---------------------------------------------------------------------------
__global__ __launch_bounds__(256, 2) void qkv_gemm_mma(
    const float* __restrict__ A, const float* __restrict__ W,
    const float* __restrict__ bias)
{
    extern __shared__ uint32_t As[];

    int tid = threadIdx.x, bm = blockIdx.x;
    int lane = tid & 31, warp = tid >> 5;
    int g = lane >> 2, t = lane & 3;
    int m0 = (warp >> 2) * 64, n0 = (warp & 3) * 32;
    int head = warp & 3;

    {
        const float4* Ap = (const float4*)(A + (size_t)bm * 128 * 128);
        for (int i = tid; i < 4096; i += 256) {
            int r = i >> 5, c = (i & 31) << 2;
            float4 v = Ap[i];
            uint4 u = make_uint4(f2tf32(v.x), f2tf32(v.y), f2tf32(v.z), f2tf32(v.w));
            *(uint4*)&As[r * A_STR + c] = u;
        }
    }

    int whbase[8], lwin8[8];
#pragma unroll
    for (int mt = 0; mt < 4; mt++)
#pragma unroll
        for (int h = 0; h < 2; h++) {
            int m = bm * 128 + m0 + mt * 16 + g + h * 8;
            int bimg = m / 3136;
            int rem  = m - bimg * 3136;
            int y = rem / 56, xx = rem - y * 56;
            int nhi = y / 7,  wy = y - nhi * 7;
            int nwi = xx / 7, wx = xx - nwi * 7;
            whbase[mt * 2 + h] = (bimg * 64 + nhi * 8 + nwi) * 4 + head;
            lwin8[mt * 2 + h]  = wy * 7 + wx;
        }
    __syncthreads();

#pragma unroll 1
    for (int s = 0; s < 3; s++) {
        const float* Wp = W + s * 128 + n0 + g;
        float acc[4][4][4] = {};

        uint32_t bv[8];
        {
            const float* w0 = Wp + (size_t)t * 384;
            const float* w1 = w0 + 4 * 384;
#pragma unroll
            for (int nt = 0; nt < 4; nt++) {
                bv[nt]     = f2tf32(__ldg(w0 + nt * 8));
                bv[4 + nt] = f2tf32(__ldg(w1 + nt * 8));
            }
        }
#pragma unroll
        for (int k0 = 0; k0 < 128; k0 += 8) {
            uint32_t bc[8];
#pragma unroll
            for (int j = 0; j < 8; j++) bc[j] = bv[j];
            if (k0 < 120) {
                const float* w0 = Wp + (size_t)(k0 + 8 + t) * 384;
                const float* w1 = w0 + 4 * 384;
#pragma unroll
                for (int nt = 0; nt < 4; nt++) {
                    bv[nt]     = f2tf32(__ldg(w0 + nt * 8));
                    bv[4 + nt] = f2tf32(__ldg(w1 + nt * 8));
                }
            }
            uint32_t a[4][4];
#pragma unroll
            for (int mt = 0; mt < 4; mt++) {
                int base = (m0 + mt * 16 + g) * A_STR + k0 + t;
                a[mt][0] = As[base];
                a[mt][1] = As[base + 8 * A_STR];
                a[mt][2] = As[base + 4];
                a[mt][3] = As[base + 8 * A_STR + 4];
            }
#pragma unroll
            for (int mt = 0; mt < 4; mt++)
#pragma unroll
                for (int nt = 0; nt < 4; nt++) {
                    uint32_t bb2[2] = {bc[nt], bc[4 + nt]};
                    mma_tf32(acc[mt][nt], a[mt], bb2);
                }
        }

        float bb[4][2];
#pragma unroll
        for (int nt = 0; nt < 4; nt++) {
            int d = nt * 8 + 2 * t;
            bb[nt][0] = bias[s * 128 + head * 32 + d];
            bb[nt][1] = bias[s * 128 + head * 32 + d + 1];
        }
#pragma unroll
        for (int mt = 0; mt < 4; mt++)
#pragma unroll
            for (int h = 0; h < 2; h++) {
                int idx = mt * 2 + h;
                size_t dst0 = ((size_t)(s * 16384 + whbase[idx]) * 49 + lwin8[idx]) * 32;
#pragma unroll
                for (int nt = 0; nt < 4; nt++) {
                    int d = nt * 8 + 2 * t;
                    uint2 v = make_uint2(f2tf32(acc[mt][nt][2 * h]     + bb[nt][0]),
                                         f2tf32(acc[mt][nt][2 * h + 1] + bb[nt][1]));
                    *(uint2*)&g_qkv[dst0 + d] = v;
                }
            }
    }
}

// ---------------------------------------------------------------------------
// Kernel 3: projection GEMM. A (g_att) already holds tf32 bits -> raw copy.
// ---------------------------------------------------------------------------
__global__ __launch_bounds__(256, 2) void proj_gemm_mma(
    const float* __restrict__ W, const float* __restrict__ bias,
    float* __restrict__ out)
{
    extern __shared__ uint32_t As[];

    int tid = threadIdx.x, bm = blockIdx.x;
    int lane = tid & 31, warp = tid >> 5;
    int g = lane >> 2, t = lane & 3;
    int m0 = (warp >> 2) * 64, n0 = (warp & 3) * 32;

    {
        const uint4* Ap = (const uint4*)(g_att + (size_t)bm * 128 * 128);
        for (int i = tid; i < 4096; i += 256) {
            int r = i >> 5, c = (i & 31) << 2;
            *(uint4*)&As[r * A_STR + c] = Ap[i];
        }
    }
    __syncthreads();

    const float* Wp = W + n0 + g;
    float acc[4][4][4] = {};
    uint32_t bv[8];
    {
        const float* w0 = Wp + (size_t)t * 128;
        const float* w1 = w0 + 4 * 128;
#pragma unroll
        for (int nt = 0; nt < 4; nt++) {
            bv[nt]     = f2tf32(__ldg(w0 + nt * 8));
            bv[4 + nt] = f2tf32(__ldg(w1 + nt * 8));
        }
    }
#pragma unroll
    for (int k0 = 0; k0 < 128; k0 += 8) {
        uint32_t bc[8];
#pragma unroll
        for (int j = 0; j < 8; j++) bc[j] = bv[j];
        if (k0 < 120) {
            const float* w0 = Wp + (size_t)(k0 + 8 + t) * 128;
            const float* w1 = w0 + 4 * 128;
#pragma unroll
            for (int nt = 0; nt < 4; nt++) {
                bv[nt]     = f2tf32(__ldg(w0 + nt * 8));
                bv[4 + nt] = f2tf32(__ldg(w1 + nt * 8));
            }
        }
        uint32_t a[4][4];
#pragma unroll
        for (int mt = 0; mt < 4; mt++) {
            int base = (m0 + mt * 16 + g) * A_STR + k0 + t;
            a[mt][0] = As[base];
            a[mt][1] = As[base + 8 * A_STR];
            a[mt][2] = As[base + 4];
            a[mt][3] = As[base + 8 * A_STR + 4];
        }
#pragma unroll
        for (int mt = 0; mt < 4; mt++)
#pragma unroll
            for (int nt = 0; nt < 4; nt++) {
                uint32_t bb2[2] = {bc[nt], bc[4 + nt]};
                mma_tf32(acc[mt][nt], a[mt], bb2);
            }
    }

    float bb[4][2];
#pragma unroll
    for (int nt = 0; nt < 4; nt++) {
        int d = n0 + nt * 8 + 2 * t;
        bb[nt][0] = bias[d];
        bb[nt][1] = bias[d + 1];
    }
#pragma unroll
    for (int mt = 0; mt < 4; mt++)
#pragma unroll
        for (int h = 0; h < 2; h++) {
            int r = m0 + mt * 16 + g + h * 8;
            float* op = out + ((size_t)bm * 128 + r) * 128;
#pragma unroll
            for (int nt = 0; nt < 4; nt++) {
                int d = n0 + nt * 8 + 2 * t;
                float2 v = make_float2(acc[mt][nt][2 * h]     + bb[nt][0],
                                       acc[mt][nt][2 * h + 1] + bb[nt][1]);
                *(float2*)&op[d] = v;
            }
        }
}

// ---------------------------------------------------------------------------
// Kernel 2: attention. One block per (window, head), 128 threads.
// In-register softmax; sP aliased onto [sQ|sK]; comb loaded after S-mma.
// ---------------------------------------------------------------------------
__global__ __launch_bounds__(128) void attn_mma()
{
    __shared__ uint32_t sQK[64 * 72];  // Q (words 0..2303, stride 36), K (2304..4607);
                                       // reused as P (stride 72) after S-mma
    __shared__ uint32_t sV[64 * 40];   // tf32 V [l][d], stride 40 (≡8 mod 32)

    uint32_t* sQ = sQK;
    uint32_t* sK = sQK + 2304;
    uint32_t* sP = sQK;

    int tid  = threadIdx.x;
    int lane = tid & 31, warp = tid >> 5;
    int g = lane >> 2, t = lane & 3;
    int wh   = blockIdx.x;
    int head = wh & 3;
    int widx = wh >> 2;
    int bimg = widx >> 6;
    int win  = widx & 63;
    const uint4* qp = (const uint4*)(g_qkv + (size_t)wh * 1568);
    const uint4* kp = (const uint4*)(g_qkv + (size_t)(16384 + wh) * 1568);
    const uint4* vp = (const uint4*)(g_qkv + (size_t)(2 * 16384 + wh) * 1568);
    const float* combp = g_comb + (size_t)(win * 4 + head) * 2401;

    // Load q/k/v (raw tf32 bits), rows l>=49 zero
    for (int idx = tid; idx < 512; idx += 128) {
        int l = idx >> 3, c4 = (idx & 7) << 2;
        uint4 z = make_uint4(0u, 0u, 0u, 0u);
        uint4 q4 = z, k4 = z, v4 = z;
        if (l < 49) {
            int e = (l * 32 + c4) >> 2;
            q4 = qp[e]; k4 = kp[e]; v4 = vp[e];
        }
        *(uint4*)&sQ[l * 36 + c4] = q4;
        *(uint4*)&sK[l * 36 + c4] = k4;
        *(uint4*)&sV[l * 40 + c4] = v4;
    }
    __syncthreads();

    int m0 = warp * 16;

    // ---- S strip (16 x 64) per warp ----
    float acc[8][4] = {};
#pragma unroll
    for (int k0 = 0; k0 < 32; k0 += 8) {
        uint32_t a[4];
        int ab = (m0 + g) * 36 + k0 + t;
        a[0] = sQ[ab];
        a[1] = sQ[ab + 8 * 36];
        a[2] = sQ[ab + 4];
        a[3] = sQ[ab + 8 * 36 + 4];
#pragma unroll
        for (int nt = 0; nt < 8; nt++) {
            uint32_t b[2];
            int bb = (nt * 8 + g) * 36 + k0 + t;   // K[n][k] gather, bank 4g+t
            b[0] = sK[bb];
            b[1] = sK[bb + 4];
            mma_tf32(acc[nt], a, b);
        }
    }

    // ---- comb loads (after mma: not live across the MMA loop) ----
    float cmb[8][4];   // [nt][2h+e]
#pragma unroll
    for (int h = 0; h < 2; h++) {
        int i = m0 + g + h * 8;
#pragma unroll
        for (int nt = 0; nt < 8; nt++)
#pragma unroll
            for (int e = 0; e < 2; e++) {
                int j = nt * 8 + 2 * t + e;
                cmb[nt][2 * h + e] = (i < 49 && j < 49)
                                   ? __ldg(combp + i * 49 + j) : -1e30f;
            }
    }

    // ---- in-register softmax (rows g, g+8 of the strip) ----
    float inv2[2];
    {
        const float scale = 0.17677669529663687f;
        float mx2[2] = {-1e30f, -1e30f};
#pragma unroll
        for (int nt = 0; nt < 8; nt++)
#pragma unroll
            for (int he = 0; he < 4; he++) {
                float v = acc[nt][he] * scale + cmb[nt][he];
                acc[nt][he] = v;
                mx2[he >> 1] = fmaxf(mx2[he >> 1], v);
            }
#pragma unroll
        for (int h = 0; h < 2; h++) {
            mx2[h] = fmaxf(mx2[h], __shfl_xor_sync(0xffffffffu, mx2[h], 1));
            mx2[h] = fmaxf(mx2[h], __shfl_xor_sync(0xffffffffu, mx2[h], 2));
        }
        float sm2[2] = {0.f, 0.f};
#pragma unroll
        for (int nt = 0; nt < 8; nt++)
#pragma unroll
            for (int he = 0; he < 4; he++) {
                float p = __expf(acc[nt][he] - mx2[he >> 1]);
                acc[nt][he] = p;
                sm2[he >> 1] += p;
            }
#pragma unroll
        for (int h = 0; h < 2; h++) {
            sm2[h] += __shfl_xor_sync(0xffffffffu, sm2[h], 1);
            sm2[h] += __shfl_xor_sync(0xffffffffu, sm2[h], 2);
        }
        inv2[0] = 1.f / sm2[0];
        inv2[1] = 1.f / sm2[1];
    }

    // barrier: all warps must be done reading sQ/sK before P overwrites them
    __syncthreads();

#pragma unroll
    for (int h = 0; h < 2; h++) {
        float inv = inv2[h];
        int row = m0 + g + h * 8;
#pragma unroll
        for (int nt = 0; nt < 8; nt++) {
            uint2 v = make_uint2(f2tf32(acc[nt][2 * h]     * inv),
                                 f2tf32(acc[nt][2 * h + 1] * inv));
            *(uint2*)&sP[row * 72 + nt * 8 + 2 * t] = v;
        }
    }
    __syncwarp();   // PV A-frag rows are this warp's own strip

    // ---- O strip (16 x 32) per warp, store tf32 bits to g_att ----
    {
        float oac[4][4] = {};
#pragma unroll
        for (int k0 = 0; k0 < 64; k0 += 8) {
            uint32_t a[4];
            int ab = (m0 + g) * 72 + k0 + t;
            a[0] = sP[ab];
            a[1] = sP[ab + 8 * 72];
            a[2] = sP[ab + 4];
            a[3] = sP[ab + 8 * 72 + 4];
#pragma unroll
            for (int nt = 0; nt < 4; nt++) {
                uint32_t b[2];
                int bb = (k0 + t) * 40 + nt * 8 + g;
                b[0] = sV[bb];
                b[1] = sV[bb + 4 * 40];
                mma_tf32(oac[nt], a, b);
            }
        }
        int ybase = (win >> 3) * 7;
        int xbase = (win & 7) * 7;
#pragma unroll
        for (int h = 0; h < 2; h++) {
            int i = m0 + g + h * 8;
            if (i < 49) {
                int wy = i / 7, wx = i - wy * 7;
                float* op = g_att + (((size_t)(bimg * 56 + ybase + wy)) * 56 + (xbase + wx)) * 128
                          + head * 32;
#pragma unroll
                for (int nt = 0; nt < 4; nt++) {
                    uint2 v = make_uint2(f2tf32(oac[nt][2 * h]),
                                         f2tf32(oac[nt][2 * h + 1]));
                    *(uint2*)&op[nt * 8 + 2 * t] = v;
                }
            }
        }
    }
}

// ---------------------------------------------------------------------------
extern "C" void kernel_launch(void* const* d_in, const int* in_sizes, int n_in,
                              void* d_out, int out_size)
{
    const float* x      = nullptr;
    const int*   relidx = nullptr;
    const float* mask   = nullptr;
    const float* qkv_w  = nullptr;
    const float* qkv_b  = nullptr;
    const float* relt   = nullptr;
    const float* proj_w = nullptr;
    const float* proj_b = nullptr;

    for (int i = 0; i < n_in; i++) {
        switch (in_sizes[i]) {
            case 25690112: x      = (const float*)d_in[i]; break;
            case 2401:     relidx = (const int*)  d_in[i]; break;
            case 153664:   mask   = (const float*)d_in[i]; break;
            case 49152:    qkv_w  = (const float*)d_in[i]; break;
            case 384:      qkv_b  = (const float*)d_in[i]; break;
            case 676:      relt   = (const float*)d_in[i]; break;
            case 16384:    proj_w = (const float*)d_in[i]; break;
            case 128:      proj_b = (const float*)d_in[i]; break;
            default: break;
        }
    }

    cudaFuncSetAttribute(qkv_gemm_mma,  cudaFuncAttributeMaxDynamicSharedMemorySize, SM_A_BYTES);
    cudaFuncSetAttribute(proj_gemm_mma, cudaFuncAttributeMaxDynamicSharedMemorySize, SM_A_BYTES);

    combine_bias<<<(COMB_ELEMS + 255) / 256, 256>>>(relidx, mask, relt);

    qkv_gemm_mma<<<TOKENS / 128, 256, SM_A_BYTES>>>(x, qkv_w, qkv_b);

    attn_mma<<<WH_TOTAL, 128>>>();

    proj_gemm_mma<<<TOKENS / 128, 256, SM_A_BYTES>>>(proj_w, proj_b, (float*)d_out);
}